// round 17
// baseline (speedup 1.0000x reference)
#include <cuda_runtime.h>
#include <cuda_fp16.h>
#include <cstdint>

// Problem constants
#define Bc 4
#define Nc 8192
#define Cc 64
#define Kc 16
#define TPB_TILES 4           // tiles (of 8 points) per CTA
#define BNS 0.99999500003749968f

// smem byte offsets
#define SO_WP   0             // 3 layers x 8nt x 4s x 32lane x 8B = 24576
#define SO_WDH  24576         // down weights fp16 [c][o] = 8192
#define SO_W1P  32768         // 64 x float4 (w1x,w1y,w1z,b1) = 1024
#define SO_BIAS 33792         // 256 floats: b2,b3,b4,bd = 1024
#define SO_PW   34816         // per-warp: rel 512 | idx 128 | y 544 | gx 4224
#define PW_STRIDE 5440
#define SMEM_TOTAL (SO_PW + 4*PW_STRIDE)   // 56576

// ---------------- device scratch ----------------
__device__ __align__(16) float g_pt[Bc*Nc*3];
__device__ __align__(16) float g_xa[Bc*Nc*Cc];
__device__ __align__(16) float g_xb[Bc*Nc*Cc];
__device__ __align__(16) uint32_t g_wpk[2*6144];   // fragment-packed fp16 weights
__device__ __align__(16) uint32_t g_wdh[2*2048];   // down weights fp16 [c][o/2]
__device__ __align__(16) float g_w1p[2*256];       // 64 x (w1x,w1y,w1z,b1)
__device__ __align__(16) float g_bias[2*256];      // b2,b3,b4,bd

// ---------------- helpers ----------------
__device__ __forceinline__ uint32_t f16x2(float lo, float hi) {
    uint32_t r;
    asm("cvt.rn.f16x2.f32 %0, %1, %2;" : "=r"(r) : "f"(hi), "f"(lo));
    return r;
}
__device__ __forceinline__ float2 uph2(uint32_t v) {
    __half2 h = *reinterpret_cast<__half2*>(&v);
    return __half22float2(h);
}
__device__ __forceinline__ void mma16816(float d[4], const uint32_t a[4],
                                         uint32_t b0, uint32_t b1) {
    asm volatile(
        "mma.sync.aligned.m16n8k16.row.col.f32.f16.f16.f32 "
        "{%0,%1,%2,%3}, {%4,%5,%6,%7}, {%8,%9}, {%0,%1,%2,%3};"
        : "+f"(d[0]), "+f"(d[1]), "+f"(d[2]), "+f"(d[3])
        : "r"(a[0]), "r"(a[1]), "r"(a[2]), "r"(a[3]), "r"(b0), "r"(b1));
}

// ---------------- fold: BN fold + fragment packing ----------------
__global__ void fold_kernel(
    const float* __restrict__ dw1, const float* __restrict__ db1,
    const float* __restrict__ dg1, const float* __restrict__ dbe1,
    const float* __restrict__ dw2, const float* __restrict__ db2,
    const float* __restrict__ dg2, const float* __restrict__ dbe2,
    const float* __restrict__ aw1, const float* __restrict__ ab1,
    const float* __restrict__ ag1, const float* __restrict__ abe1,
    const float* __restrict__ aw2, const float* __restrict__ ab2,
    const float* __restrict__ ag2, const float* __restrict__ abe2,
    const float* __restrict__ lw,  const float* __restrict__ lb,
    const float* __restrict__ lg,  const float* __restrict__ lbe)
{
    const int blk = blockIdx.x;
    const int tid = threadIdx.x;
    const float* wsrc[3] = {dw2, aw1, aw2};
    const float* gsrc[3] = {dg2, ag1, ag2};

    for (int t = tid; t < 3072; t += 256) {
        int L = t >> 10, r = t & 1023;
        int nt = r >> 7, s = (r >> 5) & 3, lane = r & 31;
        int n = nt*8 + (lane >> 2);
        int k = s*16 + (lane & 3)*2;
        float gm = gsrc[L][blk*64 + n] * BNS;
        const float* W = wsrc[L] + blk*4096 + n*64;
        unsigned short h0 = __half_as_ushort(__float2half(W[k]   * gm));
        unsigned short h1 = __half_as_ushort(__float2half(W[k+1] * gm));
        unsigned short h8 = __half_as_ushort(__float2half(W[k+8] * gm));
        unsigned short h9 = __half_as_ushort(__float2half(W[k+9] * gm));
        g_wpk[blk*6144 + t*2 + 0] = (uint32_t)h0 | ((uint32_t)h1 << 16);
        g_wpk[blk*6144 + t*2 + 1] = (uint32_t)h8 | ((uint32_t)h9 << 16);
    }
    // down weights fp16 pairs: [c][o], o-pairs packed
    for (int t = tid; t < 2048; t += 256) {
        int c = t >> 5, o = (t & 31) * 2;
        float w0 = lw[blk*4096 + o*64 + c]     * lg[blk*64 + o]   * BNS;
        float w1 = lw[blk*4096 + (o+1)*64 + c] * lg[blk*64 + o+1] * BNS;
        unsigned short h0 = __half_as_ushort(__float2half(w0));
        unsigned short h1 = __half_as_ushort(__float2half(w1));
        g_wdh[blk*2048 + t] = (uint32_t)h0 | ((uint32_t)h1 << 16);
    }
    for (int ch = tid; ch < 64; ch += 256) {
        float gm = dg1[blk*64 + ch] * BNS;
        g_w1p[blk*256 + ch*4 + 0] = dw1[blk*192 + ch*3 + 0] * gm;
        g_w1p[blk*256 + ch*4 + 1] = dw1[blk*192 + ch*3 + 1] * gm;
        g_w1p[blk*256 + ch*4 + 2] = dw1[blk*192 + ch*3 + 2] * gm;
        g_w1p[blk*256 + ch*4 + 3] = db1[blk*64 + ch] * gm + dbe1[blk*64 + ch];
    }
    for (int o = tid; o < 64; o += 256) {
        float* Bv = g_bias + blk*256;
        Bv[o]       = db2[blk*64+o]*dg2[blk*64+o]*BNS + dbe2[blk*64+o];
        Bv[64+o]    = ab1[blk*64+o]*ag1[blk*64+o]*BNS + abe1[blk*64+o];
        Bv[128+o]   = ab2[blk*64+o]*ag2[blk*64+o]*BNS + abe2[blk*64+o];
        Bv[192+o]   = lb[blk*64+o]*lg[blk*64+o]*BNS + lbe[blk*64+o];
    }
}

// ---------------- transposes ----------------
__global__ void transpose_p_kernel(const float* __restrict__ pin)
{
    int t = blockIdx.x*blockDim.x + threadIdx.x;
    if (t >= Bc*Nc) return;
    int b = t >> 13, n = t & (Nc-1);
    #pragma unroll
    for (int c = 0; c < 3; c++)
        g_pt[t*3 + c] = pin[((size_t)b*3 + c)*Nc + n];
}

__global__ void transpose_in_kernel(const float* __restrict__ src)
{
    __shared__ float tile[32][33];
    int b  = blockIdx.z;
    int n0 = blockIdx.x * 32;
    int c0 = blockIdx.y * 32;
    int tx = threadIdx.x, ty = threadIdx.y;
    #pragma unroll
    for (int i = 0; i < 32; i += 8)
        tile[ty+i][tx] = src[((size_t)b*Cc + c0+ty+i)*Nc + n0 + tx];
    __syncthreads();
    #pragma unroll
    for (int i = 0; i < 32; i += 8)
        g_xa[((size_t)b*Nc + n0+ty+i)*Cc + c0 + tx] = tile[tx][ty+i];
}

__global__ void transpose_out_kernel(float* __restrict__ dst)
{
    __shared__ float tile[32][33];
    int b  = blockIdx.z;
    int n0 = blockIdx.x * 32;
    int c0 = blockIdx.y * 32;
    int tx = threadIdx.x, ty = threadIdx.y;
    #pragma unroll
    for (int i = 0; i < 32; i += 8)
        tile[ty+i][tx] = g_xa[((size_t)b*Nc + n0+ty+i)*Cc + c0 + tx];
    __syncthreads();
    #pragma unroll
    for (int i = 0; i < 32; i += 8)
        dst[((size_t)b*Cc + c0+ty+i)*Nc + n0 + tx] = tile[tx][ty+i];
}

// ---------------- fused block kernel (warp MMA, warp-independent) ----------------
__global__ void __launch_bounds__(128, 4)
block_kernel(const int* __restrict__ idxg, int blk, int dir)
{
    const float* __restrict__ xin  = dir ? g_xb : g_xa;
    float*       __restrict__ xout = dir ? g_xa : g_xb;

    extern __shared__ float sm[];
    char* smc = (char*)sm;
    const int tid  = threadIdx.x;
    const int warp = tid >> 5;
    const int lane = tid & 31;
    const int lq   = lane & 3;    // col quad
    const int lr   = lane >> 2;   // row group 0..7

    // cooperative copy-in (only CTA-wide sync in the kernel)
    {
        const uint4* s0 = (const uint4*)(g_wpk + blk*6144);
        uint4* d0 = (uint4*)(smc + SO_WP);
        for (int t = tid; t < 1536; t += 128) d0[t] = s0[t];
        const uint4* s1 = (const uint4*)(g_wdh + blk*2048);
        uint4* d1 = (uint4*)(smc + SO_WDH);
        for (int t = tid; t < 512; t += 128) d1[t] = s1[t];
        const float4* s2 = (const float4*)(g_w1p + blk*256);
        float4* d2 = (float4*)(smc + SO_W1P);
        for (int t = tid; t < 64; t += 128) d2[t] = s2[t];
        const float4* s3 = (const float4*)(g_bias + blk*256);
        float4* d3 = (float4*)(smc + SO_BIAS);
        for (int t = tid; t < 64; t += 128) d3[t] = s3[t];
    }
    __syncthreads();

    const char* smW1 = smc + SO_W1P;
    const float* biasp = (const float*)(smc + SO_BIAS);
    char* pw = smc + SO_PW + warp*PW_STRIDE;
    float* relW = (float*)pw;                 // 32 x float4
    int*   idxW = (int*)(pw + 512);           // 32 ints
    float* yW   = (float*)(pw + 640);         // 2 x 68 floats
    uint32_t* gxS = (uint32_t*)(pw + 1184);   // 2 pts x 16 rows x (32+1) words

    for (int tt = 0; tt < TPB_TILES; ++tt) {
        const int tilebase = (blockIdx.x*TPB_TILES + tt)*8;
        const int pbase = tilebase + warp*2;      // warp's 2 points
        const int bb = pbase >> 13;

        // ---- stage idx + rel ----
        {
            int p0 = pbase + (lane >> 4);
            int nb = idxg[p0*Kc + (lane & 15)];
            idxW[lane] = nb;
            const float* pc = g_pt + (size_t)p0*3;
            const float* pn = g_pt + ((size_t)((p0 >> 13)*Nc + nb))*3;
            *(float4*)(relW + lane*4) =
                make_float4(pc[0]-pn[0], pc[1]-pn[1], pc[2]-pn[2], 0.f);
        }
        __syncwarp();

        float4 relA[2], relB[2];
        int nbA[2], nbB[2];
        #pragma unroll
        for (int mt = 0; mt < 2; mt++) {
            relA[mt] = *(float4*)(relW + (mt*16 + lr)*4);
            relB[mt] = *(float4*)(relW + (mt*16 + 8 + lr)*4);
            nbA[mt] = idxW[mt*16 + lr];
            nbB[mt] = idxW[mt*16 + 8 + lr];
        }

        // ---- gx gather -> per-warp smem (fp16), lane-private slots ----
        #pragma unroll
        for (int mt = 0; mt < 2; mt++) {
            const float* rA = xin + ((size_t)(bb*Nc + nbA[mt]))*Cc + 2*lq;
            const float* rB = xin + ((size_t)(bb*Nc + nbB[mt]))*Cc + 2*lq;
            #pragma unroll
            for (int nt = 0; nt < 8; nt++) {
                float2 a = *(const float2*)(rA + nt*8);
                float2 b = *(const float2*)(rB + nt*8);
                gxS[mt*528 + lr*33 + nt*4 + lq]       = f16x2(a.x, a.y);
                gxS[mt*528 + (lr+8)*33 + nt*4 + lq]   = f16x2(b.x, b.y);
            }
        }

        // ---- D1 (64x3 + relu) -> A fragments ----
        uint32_t af[2][4][4];
        #pragma unroll
        for (int s = 0; s < 4; s++) {
            int ch0 = s*16 + 2*lq;
            float4 w0 = *(const float4*)(smW1 + (ch0+0)*16);
            float4 w1 = *(const float4*)(smW1 + (ch0+1)*16);
            float4 w8 = *(const float4*)(smW1 + (ch0+8)*16);
            float4 w9 = *(const float4*)(smW1 + (ch0+9)*16);
            #pragma unroll
            for (int mt = 0; mt < 2; mt++) {
                float4 ra = relA[mt], rb = relB[mt];
                float vj0 = fmaxf(fmaf(ra.z,w0.z,fmaf(ra.y,w0.y,fmaf(ra.x,w0.x,w0.w))), 0.f);
                float vj1 = fmaxf(fmaf(ra.z,w1.z,fmaf(ra.y,w1.y,fmaf(ra.x,w1.x,w1.w))), 0.f);
                float vj8 = fmaxf(fmaf(ra.z,w8.z,fmaf(ra.y,w8.y,fmaf(ra.x,w8.x,w8.w))), 0.f);
                float vj9 = fmaxf(fmaf(ra.z,w9.z,fmaf(ra.y,w9.y,fmaf(ra.x,w9.x,w9.w))), 0.f);
                float uj0 = fmaxf(fmaf(rb.z,w0.z,fmaf(rb.y,w0.y,fmaf(rb.x,w0.x,w0.w))), 0.f);
                float uj1 = fmaxf(fmaf(rb.z,w1.z,fmaf(rb.y,w1.y,fmaf(rb.x,w1.x,w1.w))), 0.f);
                float uj8 = fmaxf(fmaf(rb.z,w8.z,fmaf(rb.y,w8.y,fmaf(rb.x,w8.x,w8.w))), 0.f);
                float uj9 = fmaxf(fmaf(rb.z,w9.z,fmaf(rb.y,w9.y,fmaf(rb.x,w9.x,w9.w))), 0.f);
                af[mt][s][0] = f16x2(vj0, vj1);
                af[mt][s][1] = f16x2(uj0, uj1);
                af[mt][s][2] = f16x2(vj8, vj9);
                af[mt][s][3] = f16x2(uj8, uj9);
            }
        }

        // ================= 3 tensor-core layers (nt-pair outer) =================
        #pragma unroll
        for (int L = 0; L < 3; L++) {
            const uint32_t* wpL = (const uint32_t*)(smc + SO_WP) + L*2048;
            const float* bL = biasp + L*64;
            uint32_t afn[2][4][4];
            #pragma unroll
            for (int sp = 0; sp < 4; sp++) {
                float acc[2][2][4];
                // init accumulators from bias
                #pragma unroll
                for (int j = 0; j < 2; j++) {
                    float2 bv = *(const float2*)(bL + (2*sp + j)*8 + 2*lq);
                    #pragma unroll
                    for (int mt = 0; mt < 2; mt++) {
                        acc[mt][j][0] = bv.x; acc[mt][j][1] = bv.y;
                        acc[mt][j][2] = bv.x; acc[mt][j][3] = bv.y;
                    }
                }

                #pragma unroll
                for (int s = 0; s < 4; s++) {
                    uint2 b0 = *(const uint2*)(wpL + (((2*sp  )*4 + s)*32 + lane)*2);
                    uint2 b1 = *(const uint2*)(wpL + (((2*sp+1)*4 + s)*32 + lane)*2);
                    mma16816(acc[0][0], af[0][s], b0.x, b0.y);
                    mma16816(acc[1][0], af[1][s], b0.x, b0.y);
                    mma16816(acc[0][1], af[0][s], b1.x, b1.y);
                    mma16816(acc[1][1], af[1][s], b1.x, b1.y);
                }

                if (L == 0) {
                    #pragma unroll
                    for (int mt = 0; mt < 2; mt++) {
                        #pragma unroll
                        for (int j = 0; j < 2; j++) {
                            int nt = 2*sp + j;
                            float2 ga = uph2(gxS[mt*528 + lr*33 + nt*4 + lq]);
                            float2 gb = uph2(gxS[mt*528 + (lr+8)*33 + nt*4 + lq]);
                            acc[mt][j][0] += ga.x;
                            acc[mt][j][1] += ga.y;
                            acc[mt][j][2] += gb.x;
                            acc[mt][j][3] += gb.y;
                        }
                        afn[mt][sp][0] = f16x2(acc[mt][0][0], acc[mt][0][1]);
                        afn[mt][sp][1] = f16x2(acc[mt][0][2], acc[mt][0][3]);
                        afn[mt][sp][2] = f16x2(acc[mt][1][0], acc[mt][1][1]);
                        afn[mt][sp][3] = f16x2(acc[mt][1][2], acc[mt][1][3]);
                    }
                } else if (L == 1) {
                    #pragma unroll
                    for (int mt = 0; mt < 2; mt++) {
                        #pragma unroll
                        for (int j = 0; j < 2; j++) {
                            acc[mt][j][0] = fmaxf(acc[mt][j][0], 0.f);
                            acc[mt][j][1] = fmaxf(acc[mt][j][1], 0.f);
                            acc[mt][j][2] = fmaxf(acc[mt][j][2], 0.f);
                            acc[mt][j][3] = fmaxf(acc[mt][j][3], 0.f);
                        }
                        afn[mt][sp][0] = f16x2(acc[mt][0][0], acc[mt][0][1]);
                        afn[mt][sp][1] = f16x2(acc[mt][0][2], acc[mt][0][3]);
                        afn[mt][sp][2] = f16x2(acc[mt][1][0], acc[mt][1][1]);
                        afn[mt][sp][3] = f16x2(acc[mt][1][2], acc[mt][1][3]);
                    }
                } else {
                    // relu folded into max over 16 rows (K neighbors)
                    #pragma unroll
                    for (int mt = 0; mt < 2; mt++) {
                        #pragma unroll
                        for (int j = 0; j < 2; j++) {
                            int nt = 2*sp + j;
                            float m0 = fmaxf(fmaxf(acc[mt][j][0], acc[mt][j][2]), 0.f);
                            float m1 = fmaxf(fmaxf(acc[mt][j][1], acc[mt][j][3]), 0.f);
                            #pragma unroll
                            for (int o = 4; o < 32; o <<= 1) {
                                m0 = fmaxf(m0, __shfl_xor_sync(0xffffffffu, m0, o));
                                m1 = fmaxf(m1, __shfl_xor_sync(0xffffffffu, m1, o));
                            }
                            if (lane < 4)
                                *(float2*)(yW + mt*68 + nt*8 + 2*lane) =
                                    make_float2(m0, m1);
                        }
                    }
                }
            }
            if (L < 2) {
                #pragma unroll
                for (int mt = 0; mt < 2; mt++)
                    #pragma unroll
                    for (int s = 0; s < 4; s++)
                        #pragma unroll
                        for (int e = 0; e < 4; e++)
                            af[mt][s][e] = afn[mt][s][e];
            }
        }
        __syncwarp();

        // ---- down: per-warp, fp16 weights, fp32 accumulate ----
        {
            const int dpl = lane >> 4;             // point 0/1
            const int do4 = (lane & 15) * 4;
            const int gp = pbase + dpl;
            float4 res4 = *(const float4*)(xin + (size_t)gp*Cc + do4);
            const float* yp = yW + dpl*68;
            const uint32_t* wdp = (const uint32_t*)(smc + SO_WDH);
            float4 a = *(const float4*)(biasp + 192 + do4);
            #pragma unroll 4
            for (int c = 0; c < 64; c += 4) {
                float4 yv4 = *(const float4*)(yp + c);
                #pragma unroll
                for (int cc = 0; cc < 4; cc++) {
                    uint2 wh = *(const uint2*)(wdp + ((c+cc)*64 + do4)/2);
                    float2 w01 = uph2(wh.x), w23 = uph2(wh.y);
                    float yv = (cc == 0) ? yv4.x : (cc == 1) ? yv4.y :
                               (cc == 2) ? yv4.z : yv4.w;
                    a.x = fmaf(w01.x, yv, a.x);
                    a.y = fmaf(w01.y, yv, a.y);
                    a.z = fmaf(w23.x, yv, a.z);
                    a.w = fmaf(w23.y, yv, a.w);
                }
            }
            a.x += res4.x; a.y += res4.y; a.z += res4.z; a.w += res4.w;
            *(float4*)(xout + (size_t)gp*Cc + do4) = a;
        }
        __syncwarp();
    }
}

// ---------------- launch ----------------
extern "C" void kernel_launch(void* const* d_in, const int* in_sizes, int n_in,
                              void* d_out, int out_size)
{
    const float* input_p = (const float*)d_in[0];
    const float* input_x = (const float*)d_in[1];
    const int*   idx     = (const int*)  d_in[2];
    const float* P[20];
    for (int i = 0; i < 20; i++) P[i] = (const float*)d_in[3 + i];
    float* out = (float*)d_out;

    cudaFuncSetAttribute(block_kernel,
        cudaFuncAttributeMaxDynamicSharedMemorySize, SMEM_TOTAL);

    fold_kernel<<<2, 256>>>(P[0],P[1],P[2],P[3], P[4],P[5],P[6],P[7],
                            P[8],P[9],P[10],P[11], P[12],P[13],P[14],P[15],
                            P[16],P[17],P[18],P[19]);
    transpose_p_kernel<<<(Bc*Nc + 255)/256, 256>>>(input_p);
    {
        dim3 tb(32, 8), tg(Nc/32, Cc/32, Bc);
        transpose_in_kernel<<<tg, tb>>>(input_x);
    }
    const int grid = (Bc*Nc) / (8 * TPB_TILES);   // 1024
    block_kernel<<<grid, 128, SMEM_TOTAL>>>(idx, 0, 0);  // xa -> xb
    block_kernel<<<grid, 128, SMEM_TOTAL>>>(idx, 1, 1);  // xb -> xa
    {
        dim3 tb(32, 8), tg(Nc/32, Cc/32, Bc);
        transpose_out_kernel<<<tg, tb>>>(out + Bc*3*Nc);
    }
    cudaMemcpyAsync(out, input_p, (size_t)Bc*3*Nc*sizeof(float),
                    cudaMemcpyDeviceToDevice);
}